// round 15
// baseline (speedup 1.0000x reference)
#include <cuda_runtime.h>
#include <cuda_fp16.h>
#include <cstdint>

// ---------------------------------------------------------------------------
// Problem shape (fixed by setup_inputs: B=4, S=2048, K=4096, N=4096)
// ---------------------------------------------------------------------------
namespace {
constexpr int M_DIM = 8192;
constexpr int N_DIM = 4096;
constexpr int K_DIM = 4096;
constexpr int K0C   = 256;
constexpr float TAU = 3.0f;
constexpr float EPS = 1e-6f;
constexpr float BAND = 0.05f;              // gate uncertainty band on t (~8 sigma)

// Big GEMM tiling: CTA 128x256, 8 warps (2m x 4n), warp 64x64, BK=128
constexpr int BM = 128;
constexpr int BN = 256;
constexpr int BK = 128;                     // fp16 K elems per chunk (2 x 64-col halves)
constexpr int NCHUNK = K_DIM / BK;          // 32
constexpr int A_STAGE = BM * 256;           // 32768
constexpr int B_STAGE = BN * 256;           // 65536
constexpr int STAGE2 = A_STAGE + B_STAGE;   // 98304
constexpr int SMEM_BIG = 2 * STAGE2;        // 196608

// Gate: CTA covers 128m x 128n as 2 sub-tiles of 64n. A-head (128x256 fp16,
// 64KB) resident for the whole CTA; B in a 4-stage ring of 8KB chunks.
constexpr int GBM = 128;
constexpr int GBN_SUB = 64;
constexpr int G_NSUB = 2;
constexpr int G_NITER = 4 * G_NSUB;          // 8 chunk-iterations
constexpr int G_A_BYTES = 4 * GBM * 128;     // 65536
constexpr int G_B_STAGE = GBN_SUB * 128;     // 8192
constexpr int G_B_OFF   = G_A_BYTES;         // 65536
constexpr int G_MASK_OFF = G_B_OFF + 4 * G_B_STAGE;   // 98304 (8KB stage)
constexpr int G_LBUF_OFF = G_MASK_OFF + GBM * GBN_SUB; // 106496 (1024 x u32)
constexpr int G_LBUF_CAP = 1024;
constexpr int G_LCOUNT_OFF = G_LBUF_OFF + G_LBUF_CAP * 4;  // 110592
constexpr int SMEM_GATE = 110596;            // 2 CTAs/SM
}

// ---------------------------------------------------------------------------
// Device scratch (static; no dynamic allocation allowed)
// ---------------------------------------------------------------------------
__device__ __align__(1024) unsigned char g_mask[(size_t)M_DIM * N_DIM];
__device__ __align__(1024) __half        g_Xh[(size_t)M_DIM * K_DIM];
__device__ __align__(1024) __half        g_Wh[(size_t)N_DIM * K_DIM];

// ---------------------------------------------------------------------------
// Helpers (base-ISA only: cp.async / ldmatrix / mma.sync)
// ---------------------------------------------------------------------------
__device__ __forceinline__ uint32_t smem_u32(const void* p) {
    uint32_t a;
    asm("{ .reg .u64 t; cvta.to.shared.u64 t, %1; cvt.u32.u64 %0, t; }" : "=r"(a) : "l"(p));
    return a;
}
#define SWZ128(off) ((off) ^ (((off) >> 3) & 0x70))

__device__ __forceinline__ void cp_async16(uint32_t dst, const void* src) {
    asm volatile("cp.async.cg.shared.global [%0], [%1], 16;"
                 :: "r"(dst), "l"(__cvta_generic_to_global(src)) : "memory");
}
#define CP_COMMIT() asm volatile("cp.async.commit_group;" ::: "memory")
#define CP_WAIT0()  asm volatile("cp.async.wait_group 0;" ::: "memory")
#define CP_WAIT2()  asm volatile("cp.async.wait_group 2;" ::: "memory")

__device__ __forceinline__ void ldsm_x4(uint32_t& r0, uint32_t& r1, uint32_t& r2,
                                        uint32_t& r3, uint32_t addr) {
    asm volatile("ldmatrix.sync.aligned.m8n8.x4.shared.b16 {%0,%1,%2,%3}, [%4];"
                 : "=r"(r0), "=r"(r1), "=r"(r2), "=r"(r3) : "r"(addr));
}
__device__ __forceinline__ void mma_fp16(float* c, const uint32_t* a,
                                         uint32_t b0, uint32_t b1) {
    asm volatile("mma.sync.aligned.m16n8k16.row.col.f32.f16.f16.f32 "
                 "{%0,%1,%2,%3}, {%4,%5,%6,%7}, {%8,%9}, {%0,%1,%2,%3};"
                 : "+f"(c[0]), "+f"(c[1]), "+f"(c[2]), "+f"(c[3])
                 : "r"(a[0]), "r"(a[1]), "r"(a[2]), "r"(a[3]), "r"(b0), "r"(b1));
}
__device__ __forceinline__ uint32_t sq_h2(uint32_t v) {
    uint32_t r;
    asm("mul.rn.f16x2 %0, %1, %1;" : "=r"(r) : "r"(v));
    return r;
}

// Rare-path thread-serial exact gate (overflow fallback; statistically never)
__device__ __noinline__ unsigned char exact_gate_serial(const float* __restrict__ xr,
                                                        const float* __restrict__ wr)
{
    float y = 0.0f, s = 0.0f;
    for (int k = 0; k < K0C; k += 4) {
        float4 a = *reinterpret_cast<const float4*>(xr + k);
        float4 b = *reinterpret_cast<const float4*>(wr + k);
        y = fmaf(a.x, b.x, y); y = fmaf(a.y, b.y, y);
        y = fmaf(a.z, b.z, y); y = fmaf(a.w, b.w, y);
        float px = a.x * b.x, py = a.y * b.y, pz = a.z * b.z, pw = a.w * b.w;
        s = fmaf(px, px, s); s = fmaf(py, py, s);
        s = fmaf(pz, pz, s); s = fmaf(pw, pw, s);
    }
    float denom = sqrtf(s * (1.0f / 256.0f) + EPS);
    float t = fabsf(y) / fmaxf(denom, EPS);
    return (t < TAU) ? (unsigned char)0 : (unsigned char)1;
}

// ---------------------------------------------------------------------------
// Convert: fp32 -> fp16 (RN) for both X and W. 16 floats per thread.
// ---------------------------------------------------------------------------
__global__ __launch_bounds__(256)
void conv_all(const float* __restrict__ X, const float* __restrict__ W)
{
    int idx = blockIdx.x * 256 + threadIdx.x;
    int r   = idx >> 8;
    int c   = (idx & 255) * 16;
    const float* src; __half* dst; int row;
    if (r < M_DIM) { src = X; dst = g_Xh; row = r; }
    else           { src = W; dst = g_Wh; row = r - M_DIM; }
    const float4* s = reinterpret_cast<const float4*>(src + (size_t)row * K_DIM + c);
    float4 v0 = s[0], v1 = s[1], v2 = s[2], v3 = s[3];
    uint32_t o[8];
    __half2 h;
    h = __floats2half2_rn(v0.x, v0.y); o[0] = *reinterpret_cast<uint32_t*>(&h);
    h = __floats2half2_rn(v0.z, v0.w); o[1] = *reinterpret_cast<uint32_t*>(&h);
    h = __floats2half2_rn(v1.x, v1.y); o[2] = *reinterpret_cast<uint32_t*>(&h);
    h = __floats2half2_rn(v1.z, v1.w); o[3] = *reinterpret_cast<uint32_t*>(&h);
    h = __floats2half2_rn(v2.x, v2.y); o[4] = *reinterpret_cast<uint32_t*>(&h);
    h = __floats2half2_rn(v2.z, v2.w); o[5] = *reinterpret_cast<uint32_t*>(&h);
    h = __floats2half2_rn(v3.x, v3.y); o[6] = *reinterpret_cast<uint32_t*>(&h);
    h = __floats2half2_rn(v3.z, v3.w); o[7] = *reinterpret_cast<uint32_t*>(&h);
    uint4* d = reinterpret_cast<uint4*>(dst + (size_t)row * K_DIM + c);
    d[0] = make_uint4(o[0], o[1], o[2], o[3]);
    d[1] = make_uint4(o[4], o[5], o[6], o[7]);
}

// ---------------------------------------------------------------------------
// Big GEMM + fused merge (unchanged from R14 — best measured variant).
// ---------------------------------------------------------------------------
__global__ __launch_bounds__(256, 1)
void big_gemm(float* __restrict__ Out, const float* __restrict__ Bv)
{
    extern __shared__ __align__(1024) char smem[];
    const uint32_t sbase = smem_u32(smem);
    const int tid  = threadIdx.x;
    const int wid  = tid >> 5;
    const int lane = tid & 31;

    const int bm = blockIdx.y * BM;
    const int bn = blockIdx.x * BN;

    const int warpM = (wid & 1) * 64;
    const int warpN = (wid >> 1) * 64;

    const int subl = lane >> 3;
    const int tr   = lane & 7;
    const int aRow = (subl & 1) * 8 + tr;
    const int aK8  = (subl >> 1);
    const int bRow = (subl >> 1) * 8 + tr;
    const int bK8  = (subl & 1);

    float acc[4][8][4];
    #pragma unroll
    for (int i = 0; i < 4; ++i)
        #pragma unroll
        for (int j = 0; j < 8; ++j)
            #pragma unroll
            for (int q = 0; q < 4; ++q) acc[i][j][q] = 0.0f;

    auto load_chunk = [&](int it, int buf) {
        const __half* Ap = g_Xh + (size_t)bm * K_DIM + it * BK;
        const __half* Bp = g_Wh + (size_t)bn * K_DIM + it * BK;
        const uint32_t aOff = buf * STAGE2;
        const uint32_t bOff = aOff + A_STAGE;
        #pragma unroll
        for (int l = 0; l < 8; ++l) {
            int idx  = tid + l * 256;
            int h    = idx >> 10;
            int line = idx & 1023;
            int r = line >> 3, c = line & 7;
            cp_async16(sbase + aOff + h * 16384 + SWZ128((uint32_t)(r * 128 + c * 16)),
                       Ap + (size_t)r * K_DIM + h * 64 + c * 8);
        }
        #pragma unroll
        for (int l = 0; l < 16; ++l) {
            int idx  = tid + l * 256;
            int h    = idx >> 11;
            int line = idx & 2047;
            int r = line >> 3, c = line & 7;
            cp_async16(sbase + bOff + h * 32768 + SWZ128((uint32_t)(r * 128 + c * 16)),
                       Bp + (size_t)r * K_DIM + h * 64 + c * 8);
        }
    };

    uint32_t af[2][4][4], bf[2][4][4];

    auto load_frags = [&](int ks, int slot, uint32_t aBase, uint32_t bBase) {
        const int half = ks >> 2;
        const int ksl  = ks & 3;
        const uint32_t aB = aBase + half * 16384;
        const uint32_t bB = bBase + half * 32768;
        #pragma unroll
        for (int mi = 0; mi < 4; ++mi) {
            int row = warpM + mi * 16 + aRow;
            uint32_t byte = (uint32_t)(row * 128) +
                            ((uint32_t)((ksl * 2 + aK8) * 16) ^ ((row & 7) * 16));
            ldsm_x4(af[slot][mi][0], af[slot][mi][1],
                    af[slot][mi][2], af[slot][mi][3], aB + byte);
        }
        #pragma unroll
        for (int pr = 0; pr < 4; ++pr) {
            int row = warpN + pr * 16 + bRow;
            uint32_t byte = (uint32_t)(row * 128) +
                            ((uint32_t)((ksl * 2 + bK8) * 16) ^ ((row & 7) * 16));
            ldsm_x4(bf[slot][pr][0], bf[slot][pr][1],
                    bf[slot][pr][2], bf[slot][pr][3], bB + byte);
        }
    };

    load_chunk(0, 0); CP_COMMIT();

    int buf = 0;
    for (int it = 0; it < NCHUNK; ++it) {
        CP_WAIT0();
        __syncthreads();
        if (it + 1 < NCHUNK) {
            load_chunk(it + 1, buf ^ 1);
            CP_COMMIT();
        }

        const uint32_t aBase = sbase + buf * STAGE2;
        const uint32_t bBase = aBase + A_STAGE;

        load_frags(0, 0, aBase, bBase);
        #pragma unroll
        for (int ks = 0; ks < 8; ++ks) {
            const int cur = ks & 1;
            if (ks < 7) load_frags(ks + 1, cur ^ 1, aBase, bBase);
            #pragma unroll
            for (int pr = 0; pr < 4; ++pr)
                #pragma unroll
                for (int mi = 0; mi < 4; ++mi) {
                    mma_fp16(acc[mi][pr * 2 + 0], af[cur][mi],
                             bf[cur][pr][0], bf[cur][pr][1]);
                    mma_fp16(acc[mi][pr * 2 + 1], af[cur][mi],
                             bf[cur][pr][2], bf[cur][pr][3]);
                }
        }
        buf ^= 1;
    }

    // ---- epilogue: stage mask tile + bias row into (dead) smem buffers ----
    __syncthreads();
    {
        #pragma unroll
        for (int l = 0; l < 8; ++l) {
            int idx = tid + l * 256;
            int r = idx >> 4, c = (idx & 15) * 16;
            *reinterpret_cast<uint4*>(smem + r * 256 + c) =
                *reinterpret_cast<const uint4*>(g_mask + (size_t)(bm + r) * N_DIM + bn + c);
        }
        if (tid < 64) {
            *reinterpret_cast<float4*>(smem + 32768 + tid * 16) =
                *reinterpret_cast<const float4*>(Bv + bn + tid * 4);
        }
    }
    __syncthreads();
    const unsigned char* maskS = reinterpret_cast<const unsigned char*>(smem);
    const float*         biasS = reinterpret_cast<const float*>(smem + 32768);

    const int mrow = lane >> 2;
    const int ncol = (lane & 3) * 2;
    #pragma unroll
    for (int mi = 0; mi < 4; ++mi) {
        #pragma unroll
        for (int ni = 0; ni < 8; ++ni) {
            const int mr = warpM + mi * 16 + mrow;
            const int nc = warpN + ni * 8 + ncol;
            const float bx = biasS[nc];
            const float by = biasS[nc + 1];
            size_t o  = (size_t)(bm + mr) * N_DIM + bn + nc;
            size_t o2 = o + (size_t)8 * N_DIM;
            float2 v0, v1;
            v0.x = bx + (maskS[mr * 256 + nc]           ? acc[mi][ni][0] : 0.0f);
            v0.y = by + (maskS[mr * 256 + nc + 1]       ? acc[mi][ni][1] : 0.0f);
            v1.x = bx + (maskS[(mr + 8) * 256 + nc]     ? acc[mi][ni][2] : 0.0f);
            v1.y = by + (maskS[(mr + 8) * 256 + nc + 1] ? acc[mi][ni][3] : 0.0f);
            *reinterpret_cast<float2*>(&Out[o])  = v0;
            *reinterpret_cast<float2*>(&Out[o2]) = v1;
        }
    }
}

// ---------------------------------------------------------------------------
// Gate GEMM v4: as v3, but the exact fixup is INLINED — after each sub-tile's
// mask copy-out, the CTA's warps process the local uncertain list (lbuf)
// warp-per-entry with exact fp32 recompute (identical shfl-tree arithmetic to
// the old fixup_kernel) and overwrite the mask byte in global memory.
// No global list, no separate fixup launch.
// ---------------------------------------------------------------------------
__global__ __launch_bounds__(256, 2)
void gate_gemm(const float* __restrict__ X, const float* __restrict__ W)
{
    extern __shared__ __align__(1024) char smem[];
    const uint32_t sbase = smem_u32(smem);
    const int tid  = threadIdx.x;
    const int wid  = tid >> 5;
    const int lane = tid & 31;

    const int bm = blockIdx.y * GBM;
    const int bn = blockIdx.x * (GBN_SUB * G_NSUB);

    const int warpM = (wid & 3) * 32;
    const int warpN = (wid >> 2) * 32;

    const int subl = lane >> 3;
    const int tr   = lane & 7;
    const int aRow = (subl & 1) * 8 + tr;
    const int aK8  = (subl >> 1);
    const int bRow = (subl >> 1) * 8 + tr;
    const int bK8  = (subl & 1);

    unsigned char* stage = reinterpret_cast<unsigned char*>(smem + G_MASK_OFF);
    uint32_t* lbuf  = reinterpret_cast<uint32_t*>(smem + G_LBUF_OFF);
    int* lcount = reinterpret_cast<int*>(smem + G_LCOUNT_OFF);
    if (tid == 0) *lcount = 0;

    float accY[2][4][4], accS[2][4][4];
    #pragma unroll
    for (int i = 0; i < 2; ++i)
        #pragma unroll
        for (int j = 0; j < 4; ++j)
            #pragma unroll
            for (int q = 0; q < 4; ++q) { accY[i][j][q] = 0.0f; accS[i][j][q] = 0.0f; }

    {
        #pragma unroll
        for (int l = 0; l < 16; ++l) {
            int idx = tid + l * 256;
            int chunk = idx >> 10;
            int line  = idx & 1023;
            int r = line >> 3, c = line & 7;
            cp_async16(sbase + chunk * 16384 + SWZ128((uint32_t)(r * 128 + c * 16)),
                       g_Xh + (size_t)(bm + r) * K_DIM + chunk * 64 + c * 8);
        }
    }

    auto load_B = [&](int it) {
        int sub = it >> 2, ck = it & 3;
        const __half* Bp = g_Wh + (size_t)(bn + sub * GBN_SUB) * K_DIM + ck * 64;
        const uint32_t s0 = G_B_OFF + (it & 3) * G_B_STAGE;
        #pragma unroll
        for (int l = 0; l < 2; ++l) {
            int idx = tid + l * 256;
            int r = idx >> 3, c = idx & 7;
            cp_async16(sbase + s0 + SWZ128((uint32_t)(r * 128 + c * 16)),
                       Bp + (size_t)r * K_DIM + c * 8);
        }
    };

    load_B(0); CP_COMMIT();
    load_B(1); CP_COMMIT();

    for (int it = 0; it < G_NITER; ++it) {
        if (it + 2 < G_NITER) load_B(it + 2);
        CP_COMMIT();
        CP_WAIT2();
        __syncthreads();

        const uint32_t aBase = sbase + (it & 3) * 16384;
        const uint32_t bBase = sbase + G_B_OFF + (it & 3) * G_B_STAGE;

        #pragma unroll
        for (int ks = 0; ks < 4; ++ks) {
            uint32_t ah[2][4], aq[2][4];
            #pragma unroll
            for (int mi = 0; mi < 2; ++mi) {
                int row = warpM + mi * 16 + aRow;
                uint32_t byte = (uint32_t)(row * 128) +
                                ((uint32_t)((ks * 2 + aK8) * 16) ^ ((row & 7) * 16));
                ldsm_x4(ah[mi][0], ah[mi][1], ah[mi][2], ah[mi][3], aBase + byte);
                #pragma unroll
                for (int r = 0; r < 4; ++r) aq[mi][r] = sq_h2(ah[mi][r]);
            }
            #pragma unroll
            for (int pr = 0; pr < 2; ++pr) {
                int row = warpN + pr * 16 + bRow;
                uint32_t byte = (uint32_t)(row * 128) +
                                ((uint32_t)((ks * 2 + bK8) * 16) ^ ((row & 7) * 16));
                uint32_t h0, h1, h2, h3;
                ldsm_x4(h0, h1, h2, h3, bBase + byte);
                uint32_t q0 = sq_h2(h0), q1 = sq_h2(h1);
                uint32_t q2 = sq_h2(h2), q3 = sq_h2(h3);
                #pragma unroll
                for (int mi = 0; mi < 2; ++mi) {
                    mma_fp16(accY[mi][pr * 2 + 0], ah[mi], h0, h1);
                    mma_fp16(accY[mi][pr * 2 + 1], ah[mi], h2, h3);
                    mma_fp16(accS[mi][pr * 2 + 0], aq[mi], q0, q1);
                    mma_fp16(accS[mi][pr * 2 + 1], aq[mi], q2, q3);
                }
            }
        }

        if ((it & 3) == 3) {
            // ---- classify sub-tile, stage mask, collect local uncertain list
            const int sub = it >> 2;
            const int mrow = lane >> 2;
            const int ncol = (lane & 3) * 2;
            #pragma unroll
            for (int mi = 0; mi < 2; ++mi)
                #pragma unroll
                for (int ni = 0; ni < 4; ++ni)
                    #pragma unroll
                    for (int h = 0; h < 2; ++h) {
                        const int mr = warpM + mi * 16 + mrow + h * 8;
                        const int nc = warpN + ni * 8 + ncol;
                        #pragma unroll
                        for (int q = 0; q < 2; ++q) {
                            float y = accY[mi][ni][h * 2 + q];
                            float s = accS[mi][ni][h * 2 + q];
                            float denom = sqrtf(s * (1.0f / 256.0f) + EPS);
                            float t = fabsf(y) / fmaxf(denom, EPS);
                            unsigned char mv;
                            if (t < TAU - BAND)      mv = 0;
                            else if (t > TAU + BAND) mv = 1;
                            else {
                                int li = atomicAdd(lcount, 1);
                                if (li < G_LBUF_CAP) {
                                    mv = 1;   // placeholder; inline fixup overwrites
                                    lbuf[li] = ((uint32_t)(bm + mr) << 12) |
                                               (uint32_t)(bn + sub * GBN_SUB + nc + q);
                                } else {
                                    // statistically unreachable; exact fallback
                                    mv = exact_gate_serial(
                                        X + (size_t)(bm + mr) * K_DIM,
                                        W + (size_t)(bn + sub * GBN_SUB + nc + q) * K_DIM);
                                }
                            }
                            stage[mr * 64 + nc + q] = mv;
                        }
                    }
            __syncthreads();
            // ---- coalesced mask copy-out ----
            {
                int mr = tid >> 1, half = (tid & 1) * 32;
                uint4 v0 = *reinterpret_cast<uint4*>(stage + mr * 64 + half);
                uint4 v1 = *reinterpret_cast<uint4*>(stage + mr * 64 + half + 16);
                size_t go = (size_t)(bm + mr) * N_DIM + bn + sub * GBN_SUB + half;
                *reinterpret_cast<uint4*>(g_mask + go)      = v0;
                *reinterpret_cast<uint4*>(g_mask + go + 16) = v1;
            }
            __syncthreads();
            // ---- INLINE FIXUP: warp-per-entry exact fp32 recompute ----
            {
                int ln = *lcount; if (ln > G_LBUF_CAP) ln = G_LBUF_CAP;
                for (int i = wid; i < ln; i += 8) {
                    uint32_t p = lbuf[i];
                    int m = p >> 12;
                    int n = p & 4095;
                    const float* xr = X + (size_t)m * K_DIM;
                    const float* wr = W + (size_t)n * K_DIM;
                    float y = 0.0f, s = 0.0f;
                    #pragma unroll
                    for (int j = 0; j < 2; ++j) {
                        float4 a = *reinterpret_cast<const float4*>(xr + lane * 8 + j * 4);
                        float4 b = *reinterpret_cast<const float4*>(wr + lane * 8 + j * 4);
                        y = fmaf(a.x, b.x, y); y = fmaf(a.y, b.y, y);
                        y = fmaf(a.z, b.z, y); y = fmaf(a.w, b.w, y);
                        float px = a.x * b.x, py = a.y * b.y;
                        float pz = a.z * b.z, pw = a.w * b.w;
                        s = fmaf(px, px, s); s = fmaf(py, py, s);
                        s = fmaf(pz, pz, s); s = fmaf(pw, pw, s);
                    }
                    #pragma unroll
                    for (int off = 16; off > 0; off >>= 1) {
                        y += __shfl_xor_sync(0xFFFFFFFF, y, off);
                        s += __shfl_xor_sync(0xFFFFFFFF, s, off);
                    }
                    if (lane == 0) {
                        float denom = sqrtf(s * (1.0f / 256.0f) + EPS);
                        float t = fabsf(y) / fmaxf(denom, EPS);
                        g_mask[(size_t)m * N_DIM + n] = (t < TAU) ? 0 : 1;
                    }
                }
            }
            __syncthreads();
            if (tid == 0) *lcount = 0;
            // reset accumulators for next sub-tile
            #pragma unroll
            for (int i = 0; i < 2; ++i)
                #pragma unroll
                for (int j = 0; j < 4; ++j)
                    #pragma unroll
                    for (int q = 0; q < 4; ++q) { accY[i][j][q] = 0.0f; accS[i][j][q] = 0.0f; }
        }
    }
}

// ---------------------------------------------------------------------------
extern "C" void kernel_launch(void* const* d_in, const int* in_sizes, int n_in,
                              void* d_out, int out_size)
{
    const float* x  = (const float*)d_in[0];   // [8192, 4096]
    const float* w  = (const float*)d_in[1];   // [4096, 4096]
    const float* bv = (const float*)d_in[2];   // [4096]
    float* out      = (float*)d_out;           // [8192, 4096]
    (void)in_sizes; (void)n_in; (void)out_size;

    cudaFuncSetAttribute(big_gemm,
                         cudaFuncAttributeMaxDynamicSharedMemorySize, SMEM_BIG);
    cudaFuncSetAttribute(gate_gemm,
                         cudaFuncAttributeMaxDynamicSharedMemorySize, SMEM_GATE);

    conv_all<<<(M_DIM + N_DIM) * 256 / 256, 256>>>(x, w);   // 12288 blocks

    // Gate with inlined exact fixup -> mask final in one kernel
    dim3 gateGrid(N_DIM / (GBN_SUB * G_NSUB), M_DIM / GBM);   // (32, 64)
    gate_gemm<<<gateGrid, 256, SMEM_GATE>>>(x, w);

    // Full-K value GEMM with fused mask+bias epilogue
    dim3 bigGrid(N_DIM / BN, M_DIM / BM);      // (16, 64)
    big_gemm<<<bigGrid, 256, SMEM_BIG>>>(out, bv);
}

// round 16
// speedup vs baseline: 1.0018x; 1.0018x over previous
#include <cuda_runtime.h>
#include <cuda_fp16.h>
#include <cstdint>

// ---------------------------------------------------------------------------
// Problem shape (fixed by setup_inputs: B=4, S=2048, K=4096, N=4096)
// ---------------------------------------------------------------------------
namespace {
constexpr int M_DIM = 8192;
constexpr int N_DIM = 4096;
constexpr int K_DIM = 4096;
constexpr int K0C   = 256;
constexpr float TAU = 3.0f;
constexpr float EPS = 1e-6f;
constexpr float BAND = 0.05f;              // gate uncertainty band on t (~8 sigma)

// Big GEMM tiling: CTA 128x256, 8 warps (2m x 4n), warp 64x64, BK=128
constexpr int BM = 128;
constexpr int BN = 256;
constexpr int BK = 128;                     // fp16 K elems per chunk (2 x 64-col halves)
constexpr int NCHUNK = K_DIM / BK;          // 32
constexpr int A_STAGE = BM * 256;           // 32768
constexpr int B_STAGE = BN * 256;           // 65536
constexpr int STAGE2 = A_STAGE + B_STAGE;   // 98304
constexpr int SMEM_BIG = 2 * STAGE2;        // 196608

// Gate: CTA covers 128m x 256n as 4 sub-tiles of 64n. A-head (128x256 fp16,
// 64KB) resident for the whole CTA; B in a 4-stage ring of 8KB chunks.
constexpr int GBM = 128;
constexpr int GBN_SUB = 64;
constexpr int G_NSUB = 4;                    // 4 sub-tiles -> 1024 CTAs
constexpr int G_NITER = 4 * G_NSUB;          // 16 chunk-iterations
constexpr int G_A_BYTES = 4 * GBM * 128;     // 65536
constexpr int G_B_STAGE = GBN_SUB * 128;     // 8192
constexpr int G_B_OFF   = G_A_BYTES;         // 65536
constexpr int G_MASK_OFF = G_B_OFF + 4 * G_B_STAGE;   // 98304 (8KB stage)
constexpr int G_LBUF_OFF = G_MASK_OFF + GBM * GBN_SUB; // 106496 (1024 x u32)
constexpr int G_LBUF_CAP = 1024;
constexpr int G_LCOUNT_OFF = G_LBUF_OFF + G_LBUF_CAP * 4;  // 110592
constexpr int G_LBASE_OFF  = G_LCOUNT_OFF + 4;             // 110596
constexpr int G_LNUM_OFF   = G_LBASE_OFF + 4;              // 110600
constexpr int SMEM_GATE = 110608;            // 2 CTAs/SM

constexpr int LIST_CAP = 1 << 25;           // 33.5M (full-size safe)
}

// ---------------------------------------------------------------------------
// Device scratch (static; no dynamic allocation allowed)
// ---------------------------------------------------------------------------
__device__ __align__(1024) unsigned char g_mask[(size_t)M_DIM * N_DIM];
__device__ __align__(1024) __half        g_Xh[(size_t)M_DIM * K_DIM];
__device__ __align__(1024) __half        g_Wh[(size_t)N_DIM * K_DIM];
__device__ __align__(1024) uint32_t      g_list[LIST_CAP];
__device__ int                           g_count;

// ---------------------------------------------------------------------------
// Helpers (base-ISA only: cp.async / ldmatrix / mma.sync)
// ---------------------------------------------------------------------------
__device__ __forceinline__ uint32_t smem_u32(const void* p) {
    uint32_t a;
    asm("{ .reg .u64 t; cvta.to.shared.u64 t, %1; cvt.u32.u64 %0, t; }" : "=r"(a) : "l"(p));
    return a;
}
#define SWZ128(off) ((off) ^ (((off) >> 3) & 0x70))

__device__ __forceinline__ void cp_async16(uint32_t dst, const void* src) {
    asm volatile("cp.async.cg.shared.global [%0], [%1], 16;"
                 :: "r"(dst), "l"(__cvta_generic_to_global(src)) : "memory");
}
#define CP_COMMIT() asm volatile("cp.async.commit_group;" ::: "memory")
#define CP_WAIT0()  asm volatile("cp.async.wait_group 0;" ::: "memory")
#define CP_WAIT2()  asm volatile("cp.async.wait_group 2;" ::: "memory")

__device__ __forceinline__ void ldsm_x4(uint32_t& r0, uint32_t& r1, uint32_t& r2,
                                        uint32_t& r3, uint32_t addr) {
    asm volatile("ldmatrix.sync.aligned.m8n8.x4.shared.b16 {%0,%1,%2,%3}, [%4];"
                 : "=r"(r0), "=r"(r1), "=r"(r2), "=r"(r3) : "r"(addr));
}
__device__ __forceinline__ void mma_fp16(float* c, const uint32_t* a,
                                         uint32_t b0, uint32_t b1) {
    asm volatile("mma.sync.aligned.m16n8k16.row.col.f32.f16.f16.f32 "
                 "{%0,%1,%2,%3}, {%4,%5,%6,%7}, {%8,%9}, {%0,%1,%2,%3};"
                 : "+f"(c[0]), "+f"(c[1]), "+f"(c[2]), "+f"(c[3])
                 : "r"(a[0]), "r"(a[1]), "r"(a[2]), "r"(a[3]), "r"(b0), "r"(b1));
}
__device__ __forceinline__ uint32_t sq_h2(uint32_t v) {
    uint32_t r;
    asm("mul.rn.f16x2 %0, %1, %1;" : "=r"(r) : "r"(v));
    return r;
}

// ---------------------------------------------------------------------------
// Convert: fp32 -> fp16 (RN) for both X and W. 16 floats per thread.
// Also zeroes g_count (block 0 / thread 0).
// ---------------------------------------------------------------------------
__global__ __launch_bounds__(256)
void conv_all(const float* __restrict__ X, const float* __restrict__ W)
{
    if (blockIdx.x == 0 && threadIdx.x == 0) g_count = 0;
    int idx = blockIdx.x * 256 + threadIdx.x;
    int r   = idx >> 8;
    int c   = (idx & 255) * 16;
    const float* src; __half* dst; int row;
    if (r < M_DIM) { src = X; dst = g_Xh; row = r; }
    else           { src = W; dst = g_Wh; row = r - M_DIM; }
    const float4* s = reinterpret_cast<const float4*>(src + (size_t)row * K_DIM + c);
    float4 v0 = s[0], v1 = s[1], v2 = s[2], v3 = s[3];
    uint32_t o[8];
    __half2 h;
    h = __floats2half2_rn(v0.x, v0.y); o[0] = *reinterpret_cast<uint32_t*>(&h);
    h = __floats2half2_rn(v0.z, v0.w); o[1] = *reinterpret_cast<uint32_t*>(&h);
    h = __floats2half2_rn(v1.x, v1.y); o[2] = *reinterpret_cast<uint32_t*>(&h);
    h = __floats2half2_rn(v1.z, v1.w); o[3] = *reinterpret_cast<uint32_t*>(&h);
    h = __floats2half2_rn(v2.x, v2.y); o[4] = *reinterpret_cast<uint32_t*>(&h);
    h = __floats2half2_rn(v2.z, v2.w); o[5] = *reinterpret_cast<uint32_t*>(&h);
    h = __floats2half2_rn(v3.x, v3.y); o[6] = *reinterpret_cast<uint32_t*>(&h);
    h = __floats2half2_rn(v3.z, v3.w); o[7] = *reinterpret_cast<uint32_t*>(&h);
    uint4* d = reinterpret_cast<uint4*>(dst + (size_t)row * K_DIM + c);
    d[0] = make_uint4(o[0], o[1], o[2], o[3]);
    d[1] = make_uint4(o[4], o[5], o[6], o[7]);
}

// ---------------------------------------------------------------------------
// Big GEMM + fused merge (FROZEN at R14 — best measured variant).
// ---------------------------------------------------------------------------
__global__ __launch_bounds__(256, 1)
void big_gemm(float* __restrict__ Out, const float* __restrict__ Bv)
{
    extern __shared__ __align__(1024) char smem[];
    const uint32_t sbase = smem_u32(smem);
    const int tid  = threadIdx.x;
    const int wid  = tid >> 5;
    const int lane = tid & 31;

    const int bm = blockIdx.y * BM;
    const int bn = blockIdx.x * BN;

    const int warpM = (wid & 1) * 64;
    const int warpN = (wid >> 1) * 64;

    const int subl = lane >> 3;
    const int tr   = lane & 7;
    const int aRow = (subl & 1) * 8 + tr;
    const int aK8  = (subl >> 1);
    const int bRow = (subl >> 1) * 8 + tr;
    const int bK8  = (subl & 1);

    float acc[4][8][4];
    #pragma unroll
    for (int i = 0; i < 4; ++i)
        #pragma unroll
        for (int j = 0; j < 8; ++j)
            #pragma unroll
            for (int q = 0; q < 4; ++q) acc[i][j][q] = 0.0f;

    auto load_chunk = [&](int it, int buf) {
        const __half* Ap = g_Xh + (size_t)bm * K_DIM + it * BK;
        const __half* Bp = g_Wh + (size_t)bn * K_DIM + it * BK;
        const uint32_t aOff = buf * STAGE2;
        const uint32_t bOff = aOff + A_STAGE;
        #pragma unroll
        for (int l = 0; l < 8; ++l) {
            int idx  = tid + l * 256;
            int h    = idx >> 10;
            int line = idx & 1023;
            int r = line >> 3, c = line & 7;
            cp_async16(sbase + aOff + h * 16384 + SWZ128((uint32_t)(r * 128 + c * 16)),
                       Ap + (size_t)r * K_DIM + h * 64 + c * 8);
        }
        #pragma unroll
        for (int l = 0; l < 16; ++l) {
            int idx  = tid + l * 256;
            int h    = idx >> 11;
            int line = idx & 2047;
            int r = line >> 3, c = line & 7;
            cp_async16(sbase + bOff + h * 32768 + SWZ128((uint32_t)(r * 128 + c * 16)),
                       Bp + (size_t)r * K_DIM + h * 64 + c * 8);
        }
    };

    uint32_t af[2][4][4], bf[2][4][4];

    auto load_frags = [&](int ks, int slot, uint32_t aBase, uint32_t bBase) {
        const int half = ks >> 2;
        const int ksl  = ks & 3;
        const uint32_t aB = aBase + half * 16384;
        const uint32_t bB = bBase + half * 32768;
        #pragma unroll
        for (int mi = 0; mi < 4; ++mi) {
            int row = warpM + mi * 16 + aRow;
            uint32_t byte = (uint32_t)(row * 128) +
                            ((uint32_t)((ksl * 2 + aK8) * 16) ^ ((row & 7) * 16));
            ldsm_x4(af[slot][mi][0], af[slot][mi][1],
                    af[slot][mi][2], af[slot][mi][3], aB + byte);
        }
        #pragma unroll
        for (int pr = 0; pr < 4; ++pr) {
            int row = warpN + pr * 16 + bRow;
            uint32_t byte = (uint32_t)(row * 128) +
                            ((uint32_t)((ksl * 2 + bK8) * 16) ^ ((row & 7) * 16));
            ldsm_x4(bf[slot][pr][0], bf[slot][pr][1],
                    bf[slot][pr][2], bf[slot][pr][3], bB + byte);
        }
    };

    load_chunk(0, 0); CP_COMMIT();

    int buf = 0;
    for (int it = 0; it < NCHUNK; ++it) {
        CP_WAIT0();
        __syncthreads();
        if (it + 1 < NCHUNK) {
            load_chunk(it + 1, buf ^ 1);
            CP_COMMIT();
        }

        const uint32_t aBase = sbase + buf * STAGE2;
        const uint32_t bBase = aBase + A_STAGE;

        load_frags(0, 0, aBase, bBase);
        #pragma unroll
        for (int ks = 0; ks < 8; ++ks) {
            const int cur = ks & 1;
            if (ks < 7) load_frags(ks + 1, cur ^ 1, aBase, bBase);
            #pragma unroll
            for (int pr = 0; pr < 4; ++pr)
                #pragma unroll
                for (int mi = 0; mi < 4; ++mi) {
                    mma_fp16(acc[mi][pr * 2 + 0], af[cur][mi],
                             bf[cur][pr][0], bf[cur][pr][1]);
                    mma_fp16(acc[mi][pr * 2 + 1], af[cur][mi],
                             bf[cur][pr][2], bf[cur][pr][3]);
                }
        }
        buf ^= 1;
    }

    // ---- epilogue: stage mask tile + bias row into (dead) smem buffers ----
    __syncthreads();
    {
        #pragma unroll
        for (int l = 0; l < 8; ++l) {
            int idx = tid + l * 256;
            int r = idx >> 4, c = (idx & 15) * 16;
            *reinterpret_cast<uint4*>(smem + r * 256 + c) =
                *reinterpret_cast<const uint4*>(g_mask + (size_t)(bm + r) * N_DIM + bn + c);
        }
        if (tid < 64) {
            *reinterpret_cast<float4*>(smem + 32768 + tid * 16) =
                *reinterpret_cast<const float4*>(Bv + bn + tid * 4);
        }
    }
    __syncthreads();
    const unsigned char* maskS = reinterpret_cast<const unsigned char*>(smem);
    const float*         biasS = reinterpret_cast<const float*>(smem + 32768);

    const int mrow = lane >> 2;
    const int ncol = (lane & 3) * 2;
    #pragma unroll
    for (int mi = 0; mi < 4; ++mi) {
        #pragma unroll
        for (int ni = 0; ni < 8; ++ni) {
            const int mr = warpM + mi * 16 + mrow;
            const int nc = warpN + ni * 8 + ncol;
            const float bx = biasS[nc];
            const float by = biasS[nc + 1];
            size_t o  = (size_t)(bm + mr) * N_DIM + bn + nc;
            size_t o2 = o + (size_t)8 * N_DIM;
            float2 v0, v1;
            v0.x = bx + (maskS[mr * 256 + nc]           ? acc[mi][ni][0] : 0.0f);
            v0.y = by + (maskS[mr * 256 + nc + 1]       ? acc[mi][ni][1] : 0.0f);
            v1.x = bx + (maskS[(mr + 8) * 256 + nc]     ? acc[mi][ni][2] : 0.0f);
            v1.y = by + (maskS[(mr + 8) * 256 + nc + 1] ? acc[mi][ni][3] : 0.0f);
            *reinterpret_cast<float2*>(&Out[o])  = v0;
            *reinterpret_cast<float2*>(&Out[o2]) = v1;
        }
    }
}

// ---------------------------------------------------------------------------
// Gate GEMM v5: A-head resident (64KB), 4 N-sub-tiles per CTA (1024 CTAs),
// 4-stage B ring, squares in registers, coalesced mask staging,
// CTA-aggregated uncertain list flushed per sub-tile to the global list.
// ---------------------------------------------------------------------------
__global__ __launch_bounds__(256, 2)
void gate_gemm()
{
    extern __shared__ __align__(1024) char smem[];
    const uint32_t sbase = smem_u32(smem);
    const int tid  = threadIdx.x;
    const int wid  = tid >> 5;
    const int lane = tid & 31;

    const int bm = blockIdx.y * GBM;
    const int bn = blockIdx.x * (GBN_SUB * G_NSUB);   // 256-wide CTA N footprint

    const int warpM = (wid & 3) * 32;
    const int warpN = (wid >> 2) * 32;

    const int subl = lane >> 3;
    const int tr   = lane & 7;
    const int aRow = (subl & 1) * 8 + tr;
    const int aK8  = (subl >> 1);
    const int bRow = (subl >> 1) * 8 + tr;
    const int bK8  = (subl & 1);

    unsigned char* stage = reinterpret_cast<unsigned char*>(smem + G_MASK_OFF);
    uint32_t* lbuf  = reinterpret_cast<uint32_t*>(smem + G_LBUF_OFF);
    int* lcount = reinterpret_cast<int*>(smem + G_LCOUNT_OFF);
    int* lbase  = reinterpret_cast<int*>(smem + G_LBASE_OFF);
    int* lnum   = reinterpret_cast<int*>(smem + G_LNUM_OFF);
    if (tid == 0) *lcount = 0;

    float accY[2][4][4], accS[2][4][4];
    #pragma unroll
    for (int i = 0; i < 2; ++i)
        #pragma unroll
        for (int j = 0; j < 4; ++j)
            #pragma unroll
            for (int q = 0; q < 4; ++q) { accY[i][j][q] = 0.0f; accS[i][j][q] = 0.0f; }

    {
        #pragma unroll
        for (int l = 0; l < 16; ++l) {
            int idx = tid + l * 256;
            int chunk = idx >> 10;
            int line  = idx & 1023;
            int r = line >> 3, c = line & 7;
            cp_async16(sbase + chunk * 16384 + SWZ128((uint32_t)(r * 128 + c * 16)),
                       g_Xh + (size_t)(bm + r) * K_DIM + chunk * 64 + c * 8);
        }
    }

    auto load_B = [&](int it) {
        int sub = it >> 2, ck = it & 3;
        const __half* Bp = g_Wh + (size_t)(bn + sub * GBN_SUB) * K_DIM + ck * 64;
        const uint32_t s0 = G_B_OFF + (it & 3) * G_B_STAGE;
        #pragma unroll
        for (int l = 0; l < 2; ++l) {
            int idx = tid + l * 256;
            int r = idx >> 3, c = idx & 7;
            cp_async16(sbase + s0 + SWZ128((uint32_t)(r * 128 + c * 16)),
                       Bp + (size_t)r * K_DIM + c * 8);
        }
    };

    load_B(0); CP_COMMIT();
    load_B(1); CP_COMMIT();

    for (int it = 0; it < G_NITER; ++it) {
        if (it + 2 < G_NITER) load_B(it + 2);
        CP_COMMIT();
        CP_WAIT2();
        __syncthreads();

        const uint32_t aBase = sbase + (it & 3) * 16384;
        const uint32_t bBase = sbase + G_B_OFF + (it & 3) * G_B_STAGE;

        #pragma unroll
        for (int ks = 0; ks < 4; ++ks) {
            uint32_t ah[2][4], aq[2][4];
            #pragma unroll
            for (int mi = 0; mi < 2; ++mi) {
                int row = warpM + mi * 16 + aRow;
                uint32_t byte = (uint32_t)(row * 128) +
                                ((uint32_t)((ks * 2 + aK8) * 16) ^ ((row & 7) * 16));
                ldsm_x4(ah[mi][0], ah[mi][1], ah[mi][2], ah[mi][3], aBase + byte);
                #pragma unroll
                for (int r = 0; r < 4; ++r) aq[mi][r] = sq_h2(ah[mi][r]);
            }
            #pragma unroll
            for (int pr = 0; pr < 2; ++pr) {
                int row = warpN + pr * 16 + bRow;
                uint32_t byte = (uint32_t)(row * 128) +
                                ((uint32_t)((ks * 2 + bK8) * 16) ^ ((row & 7) * 16));
                uint32_t h0, h1, h2, h3;
                ldsm_x4(h0, h1, h2, h3, bBase + byte);
                uint32_t q0 = sq_h2(h0), q1 = sq_h2(h1);
                uint32_t q2 = sq_h2(h2), q3 = sq_h2(h3);
                #pragma unroll
                for (int mi = 0; mi < 2; ++mi) {
                    mma_fp16(accY[mi][pr * 2 + 0], ah[mi], h0, h1);
                    mma_fp16(accY[mi][pr * 2 + 1], ah[mi], h2, h3);
                    mma_fp16(accS[mi][pr * 2 + 0], aq[mi], q0, q1);
                    mma_fp16(accS[mi][pr * 2 + 1], aq[mi], q2, q3);
                }
            }
        }

        if ((it & 3) == 3) {
            const int sub = it >> 2;
            const int mrow = lane >> 2;
            const int ncol = (lane & 3) * 2;
            #pragma unroll
            for (int mi = 0; mi < 2; ++mi)
                #pragma unroll
                for (int ni = 0; ni < 4; ++ni)
                    #pragma unroll
                    for (int h = 0; h < 2; ++h) {
                        const int mr = warpM + mi * 16 + mrow + h * 8;
                        const int nc = warpN + ni * 8 + ncol;
                        #pragma unroll
                        for (int q = 0; q < 2; ++q) {
                            float y = accY[mi][ni][h * 2 + q];
                            float s = accS[mi][ni][h * 2 + q];
                            float denom = sqrtf(s * (1.0f / 256.0f) + EPS);
                            float t = fabsf(y) / fmaxf(denom, EPS);
                            unsigned char mv;
                            if (t < TAU - BAND)      mv = 0;
                            else if (t > TAU + BAND) mv = 1;
                            else {
                                mv = 1;             // placeholder; fixup overwrites
                                int li = atomicAdd(lcount, 1);
                                uint32_t pk = ((uint32_t)(bm + mr) << 12) |
                                              (uint32_t)(bn + sub * GBN_SUB + nc + q);
                                if (li < G_LBUF_CAP) lbuf[li] = pk;
                                else {
                                    int gi = atomicAdd(&g_count, 1);
                                    if (gi < LIST_CAP) g_list[gi] = pk;
                                }
                            }
                            stage[mr * 64 + nc + q] = mv;
                        }
                    }
            __syncthreads();
            {
                int mr = tid >> 1, half = (tid & 1) * 32;
                uint4 v0 = *reinterpret_cast<uint4*>(stage + mr * 64 + half);
                uint4 v1 = *reinterpret_cast<uint4*>(stage + mr * 64 + half + 16);
                size_t go = (size_t)(bm + mr) * N_DIM + bn + sub * GBN_SUB + half;
                *reinterpret_cast<uint4*>(g_mask + go)      = v0;
                *reinterpret_cast<uint4*>(g_mask + go + 16) = v1;
            }
            if (tid == 0) {
                int ln = *lcount; if (ln > G_LBUF_CAP) ln = G_LBUF_CAP;
                *lbase = atomicAdd(&g_count, ln);
                *lnum  = ln;
                *lcount = 0;
            }
            __syncthreads();
            {
                int ln = *lnum, base = *lbase;
                for (int i = tid; i < ln; i += 256) {
                    int gi = base + i;
                    if (gi < LIST_CAP) g_list[gi] = lbuf[i];
                }
            }
            #pragma unroll
            for (int i = 0; i < 2; ++i)
                #pragma unroll
                for (int j = 0; j < 4; ++j)
                    #pragma unroll
                    for (int q = 0; q < 4; ++q) { accY[i][j][q] = 0.0f; accS[i][j][q] = 0.0f; }
        }
    }
}

// ---------------------------------------------------------------------------
// Fixup: exact fp32 recompute of y1/s2 for uncertain elements (1 warp each).
// ---------------------------------------------------------------------------
__global__ __launch_bounds__(256)
void fixup_kernel(const float* __restrict__ X, const float* __restrict__ W)
{
    const int lane = threadIdx.x & 31;
    const int wglobal = (blockIdx.x * 256 + threadIdx.x) >> 5;
    const int nwarps = (gridDim.x * 256) >> 5;
    int total = g_count; if (total > LIST_CAP) total = LIST_CAP;

    for (int i = wglobal; i < total; i += nwarps) {
        uint32_t p = g_list[i];
        int m = p >> 12;
        int n = p & 4095;
        const float* xr = X + (size_t)m * K_DIM;
        const float* wr = W + (size_t)n * K_DIM;
        float y = 0.0f, s = 0.0f;
        #pragma unroll
        for (int j = 0; j < 2; ++j) {
            float4 a = *reinterpret_cast<const float4*>(xr + lane * 8 + j * 4);
            float4 b = *reinterpret_cast<const float4*>(wr + lane * 8 + j * 4);
            y = fmaf(a.x, b.x, y); y = fmaf(a.y, b.y, y);
            y = fmaf(a.z, b.z, y); y = fmaf(a.w, b.w, y);
            float px = a.x * b.x, py = a.y * b.y, pz = a.z * b.z, pw = a.w * b.w;
            s = fmaf(px, px, s); s = fmaf(py, py, s);
            s = fmaf(pz, pz, s); s = fmaf(pw, pw, s);
        }
        #pragma unroll
        for (int off = 16; off > 0; off >>= 1) {
            y += __shfl_xor_sync(0xFFFFFFFF, y, off);
            s += __shfl_xor_sync(0xFFFFFFFF, s, off);
        }
        if (lane == 0) {
            float denom = sqrtf(s * (1.0f / 256.0f) + EPS);
            float t = fabsf(y) / fmaxf(denom, EPS);
            g_mask[(size_t)m * N_DIM + n] = (t < TAU) ? 0 : 1;
        }
    }
}

// ---------------------------------------------------------------------------
extern "C" void kernel_launch(void* const* d_in, const int* in_sizes, int n_in,
                              void* d_out, int out_size)
{
    const float* x  = (const float*)d_in[0];   // [8192, 4096]
    const float* w  = (const float*)d_in[1];   // [4096, 4096]
    const float* bv = (const float*)d_in[2];   // [4096]
    float* out      = (float*)d_out;           // [8192, 4096]
    (void)in_sizes; (void)n_in; (void)out_size;

    cudaFuncSetAttribute(big_gemm,
                         cudaFuncAttributeMaxDynamicSharedMemorySize, SMEM_BIG);
    cudaFuncSetAttribute(gate_gemm,
                         cudaFuncAttributeMaxDynamicSharedMemorySize, SMEM_GATE);

    conv_all<<<(M_DIM + N_DIM) * 256 / 256, 256>>>(x, w);   // 12288 blocks

    // Gate (classify + uncertain list), then exact fixup -> mask final
    dim3 gateGrid(N_DIM / (GBN_SUB * G_NSUB), M_DIM / GBM);   // (16, 64)
    gate_gemm<<<gateGrid, 256, SMEM_GATE>>>();
    fixup_kernel<<<512, 256>>>(x, w);

    // Full-K value GEMM with fused mask+bias epilogue
    dim3 bigGrid(N_DIM / BN, M_DIM / BM);      // (16, 64)
    big_gemm<<<bigGrid, 256, SMEM_BIG>>>(out, bv);
}